// round 1
// baseline (speedup 1.0000x reference)
#include <cuda_runtime.h>
#include <cuda_bf16.h>
#include <cstdint>

#define Nn 50000
#define Ee 800000
#define EF 850000   // Ee + Nn self loops
#define NEG 0.2f

// ---------------- scratch (device globals; no cudaMalloc allowed) ----------------
__device__ float    g_XL[Nn * 256];
__device__ float    g_XR[Nn * 256];
__device__ float    g_x1[Nn * 256];
__device__ float    g_x2[Nn * 256];
__device__ float    g_logits[EF * 4];
__device__ unsigned g_lmax[Nn * 4];
__device__ int      g_src[Ee];
__device__ int      g_dst[Ee];
__device__ int      g_counts[Nn];
__device__ int      g_rowstart[Nn + 1];
__device__ int      g_cursor[Nn];
__device__ int      g_csr[EF];
__device__ float    g_loopattr[Nn * 64];
__device__ int      g_is64;

// ordered-uint encoding so atomicMax works on floats of any sign
__device__ __forceinline__ unsigned ordkey(float f) {
    unsigned b = __float_as_uint(f);
    return (b & 0x80000000u) ? ~b : (b | 0x80000000u);
}
__device__ __forceinline__ float orddec(unsigned u) {
    return (u & 0x80000000u) ? __uint_as_float(u & 0x7fffffffu) : __uint_as_float(~u);
}

// ---------------- edge-index dtype detection + conversion ----------------
__global__ void detect_kernel(const void* ei) {
    if (blockIdx.x == 0 && threadIdx.x == 0) {
        const long long* p = (const long long*)ei;
        int ok = 1;
        for (int i = 0; i < 64; i++) {
            long long a = p[i], b = p[Ee + i];
            if (a < 0 || a >= Nn || b < 0 || b >= Nn) ok = 0;
        }
        g_is64 = ok;
    }
}

__global__ void convert_kernel(const void* ei) {
    int e = blockIdx.x * blockDim.x + threadIdx.x;
    if (e >= Ee) return;
    if (g_is64) {
        const long long* p = (const long long*)ei;
        g_src[e] = (int)p[e];
        g_dst[e] = (int)p[Ee + e];
    } else {
        const int* p = (const int*)ei;
        g_src[e] = p[e];
        g_dst[e] = p[Ee + e];
    }
}

// ---------------- CSR build ----------------
__global__ void zero_counts_kernel() {
    int i = blockIdx.x * blockDim.x + threadIdx.x;
    if (i < Nn) g_counts[i] = 0;
}

__global__ void count_kernel() {
    int e = blockIdx.x * blockDim.x + threadIdx.x;
    if (e < Ee) atomicAdd(&g_counts[g_dst[e]], 1);
}

// exclusive scan of (counts[i] + 1)  (the +1 reserves the self-loop slot)
__global__ void scan_kernel() {
    __shared__ int buf[1024];
    __shared__ int carry;
    int tid = threadIdx.x;
    if (tid == 0) carry = 0;
    __syncthreads();
    for (int base = 0; base < Nn; base += 1024) {
        int i = base + tid;
        int v = (i < Nn) ? (g_counts[i] + 1) : 0;
        buf[tid] = v;
        __syncthreads();
        for (int off = 1; off < 1024; off <<= 1) {
            int t = (tid >= off) ? buf[tid - off] : 0;
            __syncthreads();
            buf[tid] += t;
            __syncthreads();
        }
        int incl  = buf[tid];
        int total = buf[1023];
        if (i < Nn) g_rowstart[i] = carry + incl - v;
        __syncthreads();
        if (tid == 0) carry += total;
        __syncthreads();
    }
    if (tid == 0) g_rowstart[Nn] = carry;
}

__global__ void copy_cursor_kernel() {
    int i = blockIdx.x * blockDim.x + threadIdx.x;
    if (i < Nn) g_cursor[i] = g_rowstart[i];
}

__global__ void fill_kernel() {
    int e = blockIdx.x * blockDim.x + threadIdx.x;
    if (e >= Ee) return;
    int pos = atomicAdd(&g_cursor[g_dst[e]], 1);
    g_csr[pos] = e;
}

__global__ void selfplace_kernel() {
    int n = blockIdx.x * blockDim.x + threadIdx.x;
    if (n < Nn) g_csr[g_rowstart[n + 1] - 1] = Ee + n;
}

// loop_attr[n] = mean of edge_attr over real incoming edges of n (0 if none)
__global__ void loopattr_kernel(const float* __restrict__ eattr) {
    int n = blockIdx.x;
    int t = threadIdx.x;  // 64 threads = channel
    int s = g_rowstart[n], e1 = g_rowstart[n + 1];
    int cnt = e1 - 1 - s;  // real edges (self loop occupies last slot)
    float sum = 0.f;
    for (int j = s; j < e1 - 1; j++) {
        int e = g_csr[j];
        sum += eattr[(size_t)e * 64 + t];
    }
    g_loopattr[n * 64 + t] = sum / fmaxf((float)cnt, 1.0f);
}

// ---------------- per-layer kernels ----------------

// C[M,256] = A[M,256] @ B[256,256] + bias  (128x128x8 tiled sgemm, 8x8/thread)
__global__ void sgemm_bias(const float* __restrict__ A, const float* __restrict__ B,
                           const float* __restrict__ bias, float* __restrict__ C, int M) {
    __shared__ float As[8][128];
    __shared__ float Bs[8][128];
    int tid = threadIdx.x;
    int rowTile = blockIdx.y * 128, colTile = blockIdx.x * 128;
    int aRow = tid >> 1, aCol = (tid & 1) * 4;
    int bRow = tid >> 5, bCol = (tid & 31) * 4;
    int tr = (tid >> 4) * 8, tc = (tid & 15) * 8;
    float acc[8][8];
#pragma unroll
    for (int i = 0; i < 8; i++)
#pragma unroll
        for (int j = 0; j < 8; j++) acc[i][j] = 0.f;

    for (int k0 = 0; k0 < 256; k0 += 8) {
        float4 av = make_float4(0.f, 0.f, 0.f, 0.f);
        int gr = rowTile + aRow;
        if (gr < M) av = *(const float4*)(A + (size_t)gr * 256 + k0 + aCol);
        As[aCol + 0][aRow] = av.x;
        As[aCol + 1][aRow] = av.y;
        As[aCol + 2][aRow] = av.z;
        As[aCol + 3][aRow] = av.w;
        *(float4*)&Bs[bRow][bCol] =
            *(const float4*)(B + (size_t)(k0 + bRow) * 256 + colTile + bCol);
        __syncthreads();
#pragma unroll
        for (int kk = 0; kk < 8; kk++) {
            float af[8], bf[8];
            *(float4*)af       = *(const float4*)&As[kk][tr];
            *(float4*)(af + 4) = *(const float4*)&As[kk][tr + 4];
            *(float4*)bf       = *(const float4*)&Bs[kk][tc];
            *(float4*)(bf + 4) = *(const float4*)&Bs[kk][tc + 4];
#pragma unroll
            for (int i = 0; i < 8; i++)
#pragma unroll
                for (int j = 0; j < 8; j++)
                    acc[i][j] = fmaf(af[i], bf[j], acc[i][j]);
        }
        __syncthreads();
    }
    float4 b0 = *(const float4*)(bias + colTile + tc);
    float4 b1 = *(const float4*)(bias + colTile + tc + 4);
    float bb[8] = {b0.x, b0.y, b0.z, b0.w, b1.x, b1.y, b1.z, b1.w};
#pragma unroll
    for (int i = 0; i < 8; i++) {
        int gr = rowTile + tr + i;
        if (gr < M) {
            float4 o0 = make_float4(acc[i][0] + bb[0], acc[i][1] + bb[1],
                                    acc[i][2] + bb[2], acc[i][3] + bb[3]);
            float4 o1 = make_float4(acc[i][4] + bb[4], acc[i][5] + bb[5],
                                    acc[i][6] + bb[6], acc[i][7] + bb[7]);
            *(float4*)(C + (size_t)gr * 256 + colTile + tc)     = o0;
            *(float4*)(C + (size_t)gr * 256 + colTile + tc + 4) = o1;
        }
    }
}

__global__ void lmax_init_kernel() {
    int i = blockIdx.x * blockDim.x + threadIdx.x;
    if (i < Nn * 4) g_lmax[i] = 0u;  // ordkey of -inf-ish floor
}

// Fused edge-logit kernel: ee = eattr@We computed on the fly (We in shared,
// XOR-swizzled for conflict-free float4 LDS), 4 edges per warp for We reuse.
// Writes logits[EF,4] and atomicMax's g_lmax per (dst, head).
__global__ void logit_kernel(const float* __restrict__ eattr,
                             const float* __restrict__ We_l,
                             const float* __restrict__ att_l) {
    extern __shared__ float sWe[];  // 64*256 floats, swizzled
    int tid = threadIdx.x;
    for (int i = tid; i < (64 * 256 / 4); i += blockDim.x) {
        int lin = i * 4;
        int k = lin >> 8;
        int c = lin & 255;
        int sc = c ^ (((c >> 5) & 1) << 2);
        *(float4*)(sWe + k * 256 + sc) = ((const float4*)We_l)[i];
    }
    __syncthreads();

    int lane = tid & 31;
    int gw = (blockIdx.x * blockDim.x + tid) >> 5;
    int nw = (gridDim.x * blockDim.x) >> 5;
    int cbase = lane * 8;
    int q0 = cbase ^ (((lane >> 2) & 1) << 2);  // swizzled addr of channels cbase..+3
    int q1 = q0 ^ 4;                            // channels cbase+4..+7

    float attv[8];
    {
        float4 a0 = *(const float4*)(att_l + cbase);
        float4 a1 = *(const float4*)(att_l + cbase + 4);
        attv[0] = a0.x; attv[1] = a0.y; attv[2] = a0.z; attv[3] = a0.w;
        attv[4] = a1.x; attv[5] = a1.y; attv[6] = a1.z; attv[7] = a1.w;
    }

    for (int base = gw * 4; base < EF; base += nw * 4) {
        int srcj[4], dstj[4];
        const float* eap[4];
#pragma unroll
        for (int j = 0; j < 4; j++) {
            int e = base + j;
            if (e < EF) {
                if (e < Ee) {
                    srcj[j] = g_src[e];
                    dstj[j] = g_dst[e];
                    eap[j] = eattr + (size_t)e * 64;
                } else {
                    int nd = e - Ee;
                    srcj[j] = nd;
                    dstj[j] = nd;
                    eap[j] = g_loopattr + (size_t)nd * 64;
                }
            } else {
                srcj[j] = 0; dstj[j] = 0; eap[j] = eattr;
            }
        }
        float ea0[4], ea1[4];
#pragma unroll
        for (int j = 0; j < 4; j++) {
            ea0[j] = eap[j][lane];
            ea1[j] = eap[j][lane + 32];
        }
        float m[4][8];
#pragma unroll
        for (int j = 0; j < 4; j++)
#pragma unroll
            for (int i = 0; i < 8; i++) m[j][i] = 0.f;

#pragma unroll 8
        for (int k = 0; k < 32; k++) {
            float4 w0 = *(const float4*)(sWe + k * 256 + q0);
            float4 w1 = *(const float4*)(sWe + k * 256 + q1);
            float w[8] = {w0.x, w0.y, w0.z, w0.w, w1.x, w1.y, w1.z, w1.w};
#pragma unroll
            for (int j = 0; j < 4; j++) {
                float ev = __shfl_sync(0xffffffffu, ea0[j], k);
#pragma unroll
                for (int i = 0; i < 8; i++) m[j][i] = fmaf(ev, w[i], m[j][i]);
            }
        }
#pragma unroll 8
        for (int k = 0; k < 32; k++) {
            float4 w0 = *(const float4*)(sWe + (k + 32) * 256 + q0);
            float4 w1 = *(const float4*)(sWe + (k + 32) * 256 + q1);
            float w[8] = {w0.x, w0.y, w0.z, w0.w, w1.x, w1.y, w1.z, w1.w};
#pragma unroll
            for (int j = 0; j < 4; j++) {
                float ev = __shfl_sync(0xffffffffu, ea1[j], k);
#pragma unroll
                for (int i = 0; i < 8; i++) m[j][i] = fmaf(ev, w[i], m[j][i]);
            }
        }

#pragma unroll
        for (int j = 0; j < 4; j++) {
            int e = base + j;
            if (e < EF) {
                const float4* xl4 = (const float4*)(g_XL + (size_t)srcj[j] * 256 + cbase);
                const float4* xr4 = (const float4*)(g_XR + (size_t)dstj[j] * 256 + cbase);
                float4 la = xl4[0], lb = xl4[1], ra = xr4[0], rb = xr4[1];
                float xs[8] = {la.x + ra.x, la.y + ra.y, la.z + ra.z, la.w + ra.w,
                               lb.x + rb.x, lb.y + rb.y, lb.z + rb.z, lb.w + rb.w};
                float p = 0.f;
#pragma unroll
                for (int i = 0; i < 8; i++) {
                    float v = m[j][i] + xs[i];
                    v = (v > 0.f) ? v : NEG * v;
                    p = fmaf(v, attv[i], p);
                }
                p += __shfl_xor_sync(0xffffffffu, p, 1);
                p += __shfl_xor_sync(0xffffffffu, p, 2);
                p += __shfl_xor_sync(0xffffffffu, p, 4);
                if ((lane & 7) == 0) {
                    int h = lane >> 3;
                    g_logits[e * 4 + h] = p;
                    atomicMax(&g_lmax[dstj[j] * 4 + h], ordkey(p));
                }
            }
        }
    }
}

// Per-node softmax + aggregation: block = node, thread = channel.
// Phase 1: a = exp(logit - lmax) (in place), denom per head.
// Phase 2: out[n,c] = sum_edges alpha * XL[src,c] + bias[c].
__global__ void agg_kernel(const float* __restrict__ bias, float* __restrict__ out) {
    __shared__ float slm[4], sden[4], sinv[4];
    __shared__ int   sSrc[64];
    __shared__ float sAlf[64 * 4];
    int n = blockIdx.x;
    int tid = threadIdx.x;
    int s = g_rowstart[n], e1 = g_rowstart[n + 1];
    int deg = e1 - s;
    if (tid < 4) {
        slm[tid] = orddec(g_lmax[n * 4 + tid]);
        sden[tid] = 0.f;
    }
    __syncthreads();
    for (int idx = tid; idx < deg * 4; idx += 256) {
        int j = idx >> 2, h = idx & 3;
        int e = g_csr[s + j];
        float a = __expf(g_logits[e * 4 + h] - slm[h]);
        g_logits[e * 4 + h] = a;
        atomicAdd(&sden[h], a);
    }
    __syncthreads();
    if (tid < 4) sinv[tid] = 1.0f / sden[tid];
    __syncthreads();

    int c = tid;
    int h = c >> 6;
    float acc = 0.f;
    for (int b0 = 0; b0 < deg; b0 += 64) {
        int cnt = min(64, deg - b0);
        if (tid < cnt) {
            int e = g_csr[s + b0 + tid];
            sSrc[tid] = (e < Ee) ? g_src[e] : (e - Ee);
            sAlf[tid * 4 + 0] = g_logits[e * 4 + 0] * sinv[0];
            sAlf[tid * 4 + 1] = g_logits[e * 4 + 1] * sinv[1];
            sAlf[tid * 4 + 2] = g_logits[e * 4 + 2] * sinv[2];
            sAlf[tid * 4 + 3] = g_logits[e * 4 + 3] * sinv[3];
        }
        __syncthreads();
        for (int j2 = 0; j2 < cnt; j2++) {
            acc = fmaf(sAlf[j2 * 4 + h], g_XL[(size_t)sSrc[j2] * 256 + c], acc);
        }
        __syncthreads();
    }
    out[(size_t)n * 256 + c] = acc + bias[c];
}

// ---------------- launch ----------------
extern "C" void kernel_launch(void* const* d_in, const int* in_sizes, int n_in,
                              void* d_out, int out_size) {
    const float* x     = (const float*)d_in[0];
    const void*  ei    = d_in[1];
    const float* eattr = (const float*)d_in[2];
    const float* Wl    = (const float*)d_in[3];
    const float* bl    = (const float*)d_in[4];
    const float* Wr    = (const float*)d_in[5];
    const float* br    = (const float*)d_in[6];
    const float* We    = (const float*)d_in[7];
    const float* att   = (const float*)d_in[8];
    const float* bias  = (const float*)d_in[9];
    float* out = (float*)d_out;

    cudaFuncSetAttribute(logit_kernel, cudaFuncAttributeMaxDynamicSharedMemorySize, 65536);

    void *pXL, *pXR, *px1, *px2;
    cudaGetSymbolAddress(&pXL, g_XL);
    cudaGetSymbolAddress(&pXR, g_XR);
    cudaGetSymbolAddress(&px1, g_x1);
    cudaGetSymbolAddress(&px2, g_x2);

    const int EB = (Ee + 255) / 256;
    const int NB = (Nn + 255) / 256;

    detect_kernel<<<1, 1>>>(ei);
    convert_kernel<<<EB, 256>>>(ei);
    zero_counts_kernel<<<NB, 256>>>();
    count_kernel<<<EB, 256>>>();
    scan_kernel<<<1, 1024>>>();
    copy_cursor_kernel<<<NB, 256>>>();
    fill_kernel<<<EB, 256>>>();
    selfplace_kernel<<<NB, 256>>>();
    loopattr_kernel<<<Nn, 64>>>(eattr);

    const float* xin = x;
    for (int l = 0; l < 3; l++) {
        float* xout = (l == 0) ? (float*)px1 : (l == 1) ? (float*)px2 : out;
        dim3 gg(2, (Nn + 127) / 128);
        sgemm_bias<<<gg, 256>>>(xin, Wl + (size_t)l * 65536, bl + l * 256, (float*)pXL, Nn);
        sgemm_bias<<<gg, 256>>>(xin, Wr + (size_t)l * 65536, br + l * 256, (float*)pXR, Nn);
        lmax_init_kernel<<<(Nn * 4 + 255) / 256, 256>>>();
        logit_kernel<<<444, 256, 65536>>>(eattr, We + (size_t)l * 16384, att + l * 256);
        agg_kernel<<<Nn, 256>>>(bias + l * 256, xout);
        xin = xout;
    }
}

// round 2
// speedup vs baseline: 1.3608x; 1.3608x over previous
#include <cuda_runtime.h>
#include <cstdint>

#define Nn 50000
#define Ee 800000
#define EF 850000   // Ee + Nn self loops
#define NEG 0.2f

// ---------------- scratch (device globals; no cudaMalloc allowed) ----------------
__device__ float    g_XL[Nn * 256];
__device__ float    g_XR[Nn * 256];
__device__ float    g_x1[Nn * 256];
__device__ float    g_x2[Nn * 256];
__device__ float    g_logits[EF * 4];
__device__ unsigned g_lmax[Nn * 4];
__device__ int      g_src[Ee];
__device__ int      g_dst[Ee];
__device__ int      g_counts[Nn];
__device__ int      g_rowstart[Nn + 1];
__device__ int      g_cursor[Nn];
__device__ int      g_csr[EF];
__device__ float    g_loopattr[Nn * 64];
__device__ int      g_is64;

// ordered-uint encoding so atomicMax works on floats of any sign
__device__ __forceinline__ unsigned ordkey(float f) {
    unsigned b = __float_as_uint(f);
    return (b & 0x80000000u) ? ~b : (b | 0x80000000u);
}
__device__ __forceinline__ float orddec(unsigned u) {
    return (u & 0x80000000u) ? __uint_as_float(u & 0x7fffffffu) : __uint_as_float(~u);
}

// fp32 -> tf32 (round to nearest, bits usable as b32 mma operand)
__device__ __forceinline__ unsigned f2tf(float f) {
    unsigned u;
    asm("cvt.rna.tf32.f32 %0, %1;" : "=r"(u) : "f"(f));
    return u;
}

// m16n8k8 tf32 HMMA, fp32 accumulate
__device__ __forceinline__ void mma8(float* c, unsigned a0, unsigned a1, unsigned a2,
                                     unsigned a3, unsigned b0, unsigned b1) {
    asm volatile(
        "mma.sync.aligned.m16n8k8.row.col.f32.tf32.tf32.f32 "
        "{%0,%1,%2,%3},{%4,%5,%6,%7},{%8,%9},{%0,%1,%2,%3};"
        : "+f"(c[0]), "+f"(c[1]), "+f"(c[2]), "+f"(c[3])
        : "r"(a0), "r"(a1), "r"(a2), "r"(a3), "r"(b0), "r"(b1));
}

// k-paired smem index within a 72-uint pitch row: pairs (k, k+4) adjacent for LDS.64
__device__ __forceinline__ int pidx(int k) {
    return ((k >> 3) << 3) + ((k & 3) << 1) + ((k >> 2) & 1);
}

// ---------------- edge-index dtype detection + conversion ----------------
__global__ void detect_kernel(const void* ei) {
    if (blockIdx.x == 0 && threadIdx.x == 0) {
        const long long* p = (const long long*)ei;
        int ok = 1;
        for (int i = 0; i < 64; i++) {
            long long a = p[i], b = p[Ee - 1 - i];
            if (a < 0 || a >= Nn || b < 0 || b >= Nn) ok = 0;
        }
        g_is64 = ok;
    }
}

__global__ void convert_kernel(const void* ei) {
    int e = blockIdx.x * blockDim.x + threadIdx.x;
    if (e >= Ee) return;
    if (g_is64) {
        const long long* p = (const long long*)ei;
        g_src[e] = (int)p[e];
        g_dst[e] = (int)p[Ee + e];
    } else {
        const int* p = (const int*)ei;
        g_src[e] = p[e];
        g_dst[e] = p[Ee + e];
    }
}

// ---------------- CSR build ----------------
__global__ void zero_counts_kernel() {
    int i = blockIdx.x * blockDim.x + threadIdx.x;
    if (i < Nn) g_counts[i] = 0;
}

__global__ void count_kernel() {
    int e = blockIdx.x * blockDim.x + threadIdx.x;
    if (e < Ee) atomicAdd(&g_counts[g_dst[e]], 1);
}

__global__ void scan_kernel() {
    __shared__ int buf[1024];
    __shared__ int carry;
    int tid = threadIdx.x;
    if (tid == 0) carry = 0;
    __syncthreads();
    for (int base = 0; base < Nn; base += 1024) {
        int i = base + tid;
        int v = (i < Nn) ? (g_counts[i] + 1) : 0;
        buf[tid] = v;
        __syncthreads();
        for (int off = 1; off < 1024; off <<= 1) {
            int t = (tid >= off) ? buf[tid - off] : 0;
            __syncthreads();
            buf[tid] += t;
            __syncthreads();
        }
        int incl  = buf[tid];
        int total = buf[1023];
        if (i < Nn) g_rowstart[i] = carry + incl - v;
        __syncthreads();
        if (tid == 0) carry += total;
        __syncthreads();
    }
    if (tid == 0) g_rowstart[Nn] = carry;
}

__global__ void copy_cursor_kernel() {
    int i = blockIdx.x * blockDim.x + threadIdx.x;
    if (i < Nn) g_cursor[i] = g_rowstart[i];
}

__global__ void fill_kernel() {
    int e = blockIdx.x * blockDim.x + threadIdx.x;
    if (e >= Ee) return;
    int pos = atomicAdd(&g_cursor[g_dst[e]], 1);
    g_csr[pos] = e;
}

__global__ void selfplace_kernel() {
    int n = blockIdx.x * blockDim.x + threadIdx.x;
    if (n < Nn) g_csr[g_rowstart[n + 1] - 1] = Ee + n;
}

__global__ void loopattr_kernel(const float* __restrict__ eattr) {
    int n = blockIdx.x;
    int t = threadIdx.x;
    int s = g_rowstart[n], e1 = g_rowstart[n + 1];
    int cnt = e1 - 1 - s;
    float sum = 0.f;
    for (int j = s; j < e1 - 1; j++) {
        int e = g_csr[j];
        sum += eattr[(size_t)e * 64 + t];
    }
    g_loopattr[n * 64 + t] = sum / fmaxf((float)cnt, 1.0f);
}

// ---------------- tf32 mma GEMM: C[M,256] = A[M,256] @ W[256,256] + bias ----------
__global__ __launch_bounds__(256, 2) void xform_kernel(
    const float* __restrict__ A, const float* __restrict__ W,
    const float* __restrict__ bias, float* __restrict__ C, int M) {
    extern __shared__ unsigned sm[];
    unsigned* As = sm;             // [128][72] k-paired tf32
    unsigned* Bs = sm + 128 * 72;  // [32 kpair][128 n][2] pitch 264
    int tid = threadIdx.x, lane = tid & 31, warp = tid >> 5;
    int t = lane & 3, g = lane >> 2, wr = warp * 16;
    int row0 = blockIdx.y * 128, n0 = blockIdx.x * 128;
    float acc[16][4];
#pragma unroll
    for (int i = 0; i < 16; i++) {
        acc[i][0] = acc[i][1] = acc[i][2] = acc[i][3] = 0.f;
    }
    for (int ks = 0; ks < 256; ks += 64) {
        __syncthreads();
        for (int i = tid; i < 128 * 16; i += 256) {
            int r = i >> 4, c4 = i & 15;
            int grow = row0 + r;
            float4 v = make_float4(0.f, 0.f, 0.f, 0.f);
            if (grow < M) v = *(const float4*)(A + (size_t)grow * 256 + ks + c4 * 4);
            int kb = c4 * 4;
            As[r * 72 + pidx(kb + 0)] = f2tf(v.x);
            As[r * 72 + pidx(kb + 1)] = f2tf(v.y);
            As[r * 72 + pidx(kb + 2)] = f2tf(v.z);
            As[r * 72 + pidx(kb + 3)] = f2tf(v.w);
        }
        for (int i = tid; i < 64 * 32; i += 256) {
            int k = i >> 5, n4 = i & 31;
            float4 v = *(const float4*)(W + (size_t)(ks + k) * 256 + n0 + n4 * 4);
            int kp = ((k >> 3) << 2) + (k & 3);
            int sl = (k >> 2) & 1;
            unsigned* bp = Bs + kp * 264 + sl;
            bp[(n4 * 4 + 0) * 2] = f2tf(v.x);
            bp[(n4 * 4 + 1) * 2] = f2tf(v.y);
            bp[(n4 * 4 + 2) * 2] = f2tf(v.z);
            bp[(n4 * 4 + 3) * 2] = f2tf(v.w);
        }
        __syncthreads();
#pragma unroll
        for (int k8 = 0; k8 < 8; k8++) {
            uint2 pa = *(uint2*)&As[(wr + g) * 72 + k8 * 8 + t * 2];
            uint2 pb = *(uint2*)&As[(wr + g + 8) * 72 + k8 * 8 + t * 2];
#pragma unroll
            for (int nt = 0; nt < 16; nt++) {
                uint2 bb = *(uint2*)&Bs[(k8 * 4 + t) * 264 + (nt * 8 + g) * 2];
                mma8(acc[nt], pa.x, pb.x, pa.y, pb.y, bb.x, bb.y);
            }
        }
    }
#pragma unroll
    for (int nt = 0; nt < 16; nt++) {
        int c = n0 + nt * 8 + t * 2;
        float2 bv = *(const float2*)(bias + c);
        int r0 = row0 + wr + g, r1 = r0 + 8;
        if (r0 < M) {
            float2 o = make_float2(acc[nt][0] + bv.x, acc[nt][1] + bv.y);
            *(float2*)(C + (size_t)r0 * 256 + c) = o;
        }
        if (r1 < M) {
            float2 o = make_float2(acc[nt][2] + bv.x, acc[nt][3] + bv.y);
            *(float2*)(C + (size_t)r1 * 256 + c) = o;
        }
    }
}

__global__ void lmax_init_kernel() {
    int i = blockIdx.x * blockDim.x + threadIdx.x;
    if (i < Nn * 4) g_lmax[i] = 0u;
}

// ---------------- fused edge logits via tf32 mma ----------------
// EE = eattr@We (on the fly), m = EE + XL[src] + XR[dst], logits = lrelu(m)·att,
// plus per-(dst,head) atomicMax. 128 edges per tile, persistent blocks.
__global__ __launch_bounds__(256, 2) void logit_mma_kernel(
    const float* __restrict__ eattr, const float* __restrict__ We_l,
    const float* __restrict__ att_l) {
    extern __shared__ unsigned sm[];
    unsigned* sWe = sm;              // [32 kpair][256 n][2] pitch 520
    unsigned* As  = sm + 32 * 520;   // [128][72]
    float* satt = (float*)(As + 128 * 72);  // 256
    int* sSrc = (int*)(satt + 256);         // 128
    int* sDst = sSrc + 128;                 // 128
    int tid = threadIdx.x, lane = tid & 31, warp = tid >> 5;
    int t = lane & 3, g = lane >> 2, wr = warp * 16;

    for (int i = tid; i < 4096; i += 256) {  // 64x256 floats = 4096 float4
        int k = i >> 6, n4 = i & 63;
        float4 v = *(const float4*)(We_l + (size_t)k * 256 + n4 * 4);
        int kp = ((k >> 3) << 2) + (k & 3);
        int sl = (k >> 2) & 1;
        unsigned* bp = sWe + kp * 520 + sl;
        bp[(n4 * 4 + 0) * 2] = f2tf(v.x);
        bp[(n4 * 4 + 1) * 2] = f2tf(v.y);
        bp[(n4 * 4 + 2) * 2] = f2tf(v.z);
        bp[(n4 * 4 + 3) * 2] = f2tf(v.w);
    }
    if (tid < 256) satt[tid] = att_l[tid];

    int ntiles = (EF + 127) / 128;
    for (int tile = blockIdx.x; tile < ntiles; tile += gridDim.x) {
        int base = tile * 128;
        __syncthreads();
        for (int i = tid; i < 128 * 16; i += 256) {
            int r = i >> 4, c4 = i & 15;
            int e = base + r;
            float4 v = make_float4(0.f, 0.f, 0.f, 0.f);
            if (e < Ee)      v = *(const float4*)(eattr + (size_t)e * 64 + c4 * 4);
            else if (e < EF) v = *(const float4*)(g_loopattr + (size_t)(e - Ee) * 64 + c4 * 4);
            int kb = c4 * 4;
            As[r * 72 + pidx(kb + 0)] = f2tf(v.x);
            As[r * 72 + pidx(kb + 1)] = f2tf(v.y);
            As[r * 72 + pidx(kb + 2)] = f2tf(v.z);
            As[r * 72 + pidx(kb + 3)] = f2tf(v.w);
        }
        if (tid < 128) {
            int e = base + tid;
            int s = 0, d = 0;
            if (e < Ee)      { s = g_src[e]; d = g_dst[e]; }
            else if (e < EF) { s = d = e - Ee; }
            sSrc[tid] = s;
            sDst[tid] = d;
        }
        __syncthreads();

        unsigned a0[8], a1[8], a2[8], a3[8];
#pragma unroll
        for (int k8 = 0; k8 < 8; k8++) {
            uint2 pa = *(uint2*)&As[(wr + g) * 72 + k8 * 8 + t * 2];
            uint2 pb = *(uint2*)&As[(wr + g + 8) * 72 + k8 * 8 + t * 2];
            a0[k8] = pa.x; a2[k8] = pa.y;
            a1[k8] = pb.x; a3[k8] = pb.y;
        }
        int r0 = wr + g, r1 = wr + g + 8;
        int e0 = base + r0, e1 = base + r1;
        int s0 = sSrc[r0], d0 = sDst[r0];
        int s1 = sSrc[r1], d1 = sDst[r1];

#pragma unroll
        for (int h = 0; h < 4; h++) {
            float acc[8][4];
#pragma unroll
            for (int nt = 0; nt < 8; nt++) {
                acc[nt][0] = acc[nt][1] = acc[nt][2] = acc[nt][3] = 0.f;
            }
#pragma unroll
            for (int k8 = 0; k8 < 8; k8++) {
#pragma unroll
                for (int nt = 0; nt < 8; nt++) {
                    uint2 bb = *(uint2*)&sWe[(k8 * 4 + t) * 520 + (h * 64 + nt * 8 + g) * 2];
                    mma8(acc[nt], a0[k8], a1[k8], a2[k8], a3[k8], bb.x, bb.y);
                }
            }
            float p0 = 0.f, p1 = 0.f;
#pragma unroll
            for (int nt = 0; nt < 8; nt++) {
                int c = h * 64 + nt * 8 + t * 2;
                float2 av  = *(float2*)&satt[c];
                float2 xl0 = *(const float2*)(g_XL + (size_t)s0 * 256 + c);
                float2 xr0 = *(const float2*)(g_XR + (size_t)d0 * 256 + c);
                float2 xl1 = *(const float2*)(g_XL + (size_t)s1 * 256 + c);
                float2 xr1 = *(const float2*)(g_XR + (size_t)d1 * 256 + c);
                float v;
                v = acc[nt][0] + xl0.x + xr0.x; v = fmaxf(v, 0.f) + NEG * fminf(v, 0.f); p0 = fmaf(v, av.x, p0);
                v = acc[nt][1] + xl0.y + xr0.y; v = fmaxf(v, 0.f) + NEG * fminf(v, 0.f); p0 = fmaf(v, av.y, p0);
                v = acc[nt][2] + xl1.x + xr1.x; v = fmaxf(v, 0.f) + NEG * fminf(v, 0.f); p1 = fmaf(v, av.x, p1);
                v = acc[nt][3] + xl1.y + xr1.y; v = fmaxf(v, 0.f) + NEG * fminf(v, 0.f); p1 = fmaf(v, av.y, p1);
            }
            p0 += __shfl_xor_sync(0xffffffffu, p0, 1);
            p0 += __shfl_xor_sync(0xffffffffu, p0, 2);
            p1 += __shfl_xor_sync(0xffffffffu, p1, 1);
            p1 += __shfl_xor_sync(0xffffffffu, p1, 2);
            if (t == 0) {
                if (e0 < EF) {
                    g_logits[e0 * 4 + h] = p0;
                    atomicMax(&g_lmax[d0 * 4 + h], ordkey(p0));
                }
                if (e1 < EF) {
                    g_logits[e1 * 4 + h] = p1;
                    atomicMax(&g_lmax[d1 * 4 + h], ordkey(p1));
                }
            }
        }
    }
}

// ---------------- per-node softmax + aggregation ----------------
__global__ void agg_kernel(const float* __restrict__ bias, float* __restrict__ out) {
    __shared__ float slm[4], sden[4], sinv[4];
    __shared__ int   sSrc[64];
    __shared__ float sAlf[64 * 4];
    int n = blockIdx.x;
    int tid = threadIdx.x;
    int s = g_rowstart[n], e1 = g_rowstart[n + 1];
    int deg = e1 - s;
    if (tid < 4) {
        slm[tid] = orddec(g_lmax[n * 4 + tid]);
        sden[tid] = 0.f;
    }
    __syncthreads();
    for (int idx = tid; idx < deg * 4; idx += 256) {
        int j = idx >> 2, h = idx & 3;
        int e = g_csr[s + j];
        float a = __expf(g_logits[e * 4 + h] - slm[h]);
        g_logits[e * 4 + h] = a;
        atomicAdd(&sden[h], a);
    }
    __syncthreads();
    if (tid < 4) sinv[tid] = 1.0f / sden[tid];
    __syncthreads();

    int c = tid;
    int h = c >> 6;
    float acc = 0.f;
    for (int b0 = 0; b0 < deg; b0 += 64) {
        int cnt = min(64, deg - b0);
        if (tid < cnt) {
            int e = g_csr[s + b0 + tid];
            sSrc[tid] = (e < Ee) ? g_src[e] : (e - Ee);
            sAlf[tid * 4 + 0] = g_logits[e * 4 + 0] * sinv[0];
            sAlf[tid * 4 + 1] = g_logits[e * 4 + 1] * sinv[1];
            sAlf[tid * 4 + 2] = g_logits[e * 4 + 2] * sinv[2];
            sAlf[tid * 4 + 3] = g_logits[e * 4 + 3] * sinv[3];
        }
        __syncthreads();
        for (int j2 = 0; j2 < cnt; j2++) {
            acc = fmaf(sAlf[j2 * 4 + h], g_XL[(size_t)sSrc[j2] * 256 + c], acc);
        }
        __syncthreads();
    }
    out[(size_t)n * 256 + c] = acc + bias[c];
}

// ---------------- launch ----------------
extern "C" void kernel_launch(void* const* d_in, const int* in_sizes, int n_in,
                              void* d_out, int out_size) {
    const float* x     = (const float*)d_in[0];
    const void*  ei    = d_in[1];
    const float* eattr = (const float*)d_in[2];
    const float* Wl    = (const float*)d_in[3];
    const float* bl    = (const float*)d_in[4];
    const float* Wr    = (const float*)d_in[5];
    const float* br    = (const float*)d_in[6];
    const float* We    = (const float*)d_in[7];
    const float* att   = (const float*)d_in[8];
    const float* bias  = (const float*)d_in[9];
    float* out = (float*)d_out;

    const int LOGIT_SMEM = (32 * 520 + 128 * 72) * 4 + 256 * 4 + 128 * 4 * 2;  // 105472
    const int XFORM_SMEM = (128 * 72 + 32 * 264) * 4;                          // 70656
    cudaFuncSetAttribute(logit_mma_kernel, cudaFuncAttributeMaxDynamicSharedMemorySize, LOGIT_SMEM);
    cudaFuncSetAttribute(xform_kernel, cudaFuncAttributeMaxDynamicSharedMemorySize, XFORM_SMEM);

    void *pXL, *pXR, *px1, *px2;
    cudaGetSymbolAddress(&pXL, g_XL);
    cudaGetSymbolAddress(&pXR, g_XR);
    cudaGetSymbolAddress(&px1, g_x1);
    cudaGetSymbolAddress(&px2, g_x2);

    const int EB = (Ee + 255) / 256;
    const int NB = (Nn + 255) / 256;

    detect_kernel<<<1, 1>>>(ei);
    convert_kernel<<<EB, 256>>>(ei);
    zero_counts_kernel<<<NB, 256>>>();
    count_kernel<<<EB, 256>>>();
    scan_kernel<<<1, 1024>>>();
    copy_cursor_kernel<<<NB, 256>>>();
    fill_kernel<<<EB, 256>>>();
    selfplace_kernel<<<NB, 256>>>();
    loopattr_kernel<<<Nn, 64>>>(eattr);

    const float* xin = x;
    for (int l = 0; l < 3; l++) {
        float* xout = (l == 0) ? (float*)px1 : (l == 1) ? (float*)px2 : out;
        dim3 gg(2, (Nn + 127) / 128);
        xform_kernel<<<gg, 256, XFORM_SMEM>>>(xin, Wl + (size_t)l * 65536, bl + l * 256, (float*)pXL, Nn);
        xform_kernel<<<gg, 256, XFORM_SMEM>>>(xin, Wr + (size_t)l * 65536, br + l * 256, (float*)pXR, Nn);
        lmax_init_kernel<<<(Nn * 4 + 255) / 256, 256>>>();
        logit_mma_kernel<<<296, 256, LOGIT_SMEM>>>(eattr, We + (size_t)l * 16384, att + l * 256);
        agg_kernel<<<Nn, 256>>>(bias + l * 256, xout);
        xin = xout;
    }
}

// round 4
// speedup vs baseline: 1.5143x; 1.1128x over previous
#include <cuda_runtime.h>
#include <cstdint>

#define Nn 50000
#define Ee 800000
#define EF 850000   // Ee + Nn self loops
#define NEG 0.2f

// ---------------- scratch (device globals; no cudaMalloc allowed) ----------------
__device__ float    g_XL[Nn * 256];
__device__ float    g_XR[Nn * 256];
__device__ float    g_x1[Nn * 256];
__device__ float    g_x2[Nn * 256];
__device__ float    g_logits[EF * 4];
__device__ unsigned g_lmax[Nn * 4];
__device__ float    g_den[Nn * 4];
__device__ int      g_src[Ee];
__device__ int      g_dst[Ee];
__device__ int      g_counts[Nn];
__device__ int      g_rowstart[Nn + 1];
__device__ int      g_cursor[Nn];
__device__ int      g_csr[EF];
__device__ float    g_loopattr[Nn * 64];
__device__ int      g_is64;

__device__ __forceinline__ unsigned ordkey(float f) {
    unsigned b = __float_as_uint(f);
    return (b & 0x80000000u) ? ~b : (b | 0x80000000u);
}
__device__ __forceinline__ float orddec(unsigned u) {
    return (u & 0x80000000u) ? __uint_as_float(u & 0x7fffffffu) : __uint_as_float(~u);
}

__device__ __forceinline__ unsigned f2tf(float f) {
    unsigned u;
    asm("cvt.rna.tf32.f32 %0, %1;" : "=r"(u) : "f"(f));
    return u;
}

__device__ __forceinline__ void mma8(float* c, unsigned a0, unsigned a1, unsigned a2,
                                     unsigned a3, unsigned b0, unsigned b1) {
    asm volatile(
        "mma.sync.aligned.m16n8k8.row.col.f32.tf32.tf32.f32 "
        "{%0,%1,%2,%3},{%4,%5,%6,%7},{%8,%9},{%0,%1,%2,%3};"
        : "+f"(c[0]), "+f"(c[1]), "+f"(c[2]), "+f"(c[3])
        : "r"(a0), "r"(a1), "r"(a2), "r"(a3), "r"(b0), "r"(b1));
}

__device__ __forceinline__ int pidx(int k) {
    return ((k >> 3) << 3) + ((k & 3) << 1) + ((k >> 2) & 1);
}

__device__ __forceinline__ float4 ldcs4(const float* p) {
    float4 v;
    asm("ld.global.cs.v4.f32 {%0,%1,%2,%3}, [%4];"
        : "=f"(v.x), "=f"(v.y), "=f"(v.z), "=f"(v.w) : "l"(p));
    return v;
}

#define BARG(id) asm volatile("bar.sync %0, 64;" :: "r"(id) : "memory")

// ---------------- edge-index dtype detection + conversion ----------------
__global__ void detect_kernel(const void* ei) {
    if (blockIdx.x == 0 && threadIdx.x == 0) {
        const long long* p = (const long long*)ei;
        int ok = 1;
        for (int i = 0; i < 64; i++) {
            long long a = p[i], b = p[Ee - 1 - i];
            if (a < 0 || a >= Nn || b < 0 || b >= Nn) ok = 0;
        }
        g_is64 = ok;
    }
}

__global__ void convert_kernel(const void* ei) {
    int e = blockIdx.x * blockDim.x + threadIdx.x;
    if (e >= Ee) return;
    if (g_is64) {
        const long long* p = (const long long*)ei;
        g_src[e] = (int)p[e];
        g_dst[e] = (int)p[Ee + e];
    } else {
        const int* p = (const int*)ei;
        g_src[e] = p[e];
        g_dst[e] = p[Ee + e];
    }
}

// ---------------- CSR build ----------------
__global__ void zero_counts_kernel() {
    int i = blockIdx.x * blockDim.x + threadIdx.x;
    if (i < Nn) g_counts[i] = 0;
}

__global__ void count_kernel() {
    int e = blockIdx.x * blockDim.x + threadIdx.x;
    if (e < Ee) atomicAdd(&g_counts[g_dst[e]], 1);
}

__global__ void scan_kernel() {
    __shared__ int buf[1024];
    __shared__ int carry;
    int tid = threadIdx.x;
    if (tid == 0) carry = 0;
    __syncthreads();
    for (int base = 0; base < Nn; base += 1024) {
        int i = base + tid;
        int v = (i < Nn) ? (g_counts[i] + 1) : 0;
        buf[tid] = v;
        __syncthreads();
        for (int off = 1; off < 1024; off <<= 1) {
            int t = (tid >= off) ? buf[tid - off] : 0;
            __syncthreads();
            buf[tid] += t;
            __syncthreads();
        }
        int incl  = buf[tid];
        int total = buf[1023];
        if (i < Nn) g_rowstart[i] = carry + incl - v;
        __syncthreads();
        if (tid == 0) carry += total;
        __syncthreads();
    }
    if (tid == 0) g_rowstart[Nn] = carry;
}

__global__ void copy_cursor_kernel() {
    int i = blockIdx.x * blockDim.x + threadIdx.x;
    if (i < Nn) g_cursor[i] = g_rowstart[i];
}

__global__ void fill_kernel() {
    int e = blockIdx.x * blockDim.x + threadIdx.x;
    if (e >= Ee) return;
    int pos = atomicAdd(&g_cursor[g_dst[e]], 1);
    g_csr[pos] = e;
}

__global__ void selfplace_kernel() {
    int n = blockIdx.x * blockDim.x + threadIdx.x;
    if (n < Nn) g_csr[g_rowstart[n + 1] - 1] = Ee + n;
}

__global__ void loopattr_kernel(const float* __restrict__ eattr) {
    int n = blockIdx.x;
    int t = threadIdx.x;
    int s = g_rowstart[n], e1 = g_rowstart[n + 1];
    int cnt = e1 - 1 - s;
    float sum = 0.f;
    for (int j = s; j < e1 - 1; j++) {
        int e = g_csr[j];
        sum += __ldcs(eattr + (size_t)e * 64 + t);
    }
    g_loopattr[n * 64 + t] = sum / fmaxf((float)cnt, 1.0f);
}

// ---------------- tf32 mma GEMM: C[M,256] = A[M,256] @ W[256,256] + bias ----------
// blockIdx.z: 0 -> (Wl, bl, XL), 1 -> (Wr, br, XR)
__global__ __launch_bounds__(256, 2) void xform_kernel(
    const float* __restrict__ A,
    const float* __restrict__ Wl_l, const float* __restrict__ bl_l,
    const float* __restrict__ Wr_l, const float* __restrict__ br_l,
    float* __restrict__ XLp, float* __restrict__ XRp, int M) {
    extern __shared__ unsigned sm[];
    unsigned* As = sm;             // [128][72] k-paired tf32
    unsigned* Bs = sm + 128 * 72;  // [32 kpair][128 n][2] pitch 264
    const float* W    = blockIdx.z ? Wr_l : Wl_l;
    const float* bias = blockIdx.z ? br_l : bl_l;
    float* C          = blockIdx.z ? XRp  : XLp;
    int tid = threadIdx.x, lane = tid & 31, warp = tid >> 5;
    int t = lane & 3, g = lane >> 2, wr = warp * 16;
    int row0 = blockIdx.y * 128, n0 = blockIdx.x * 128;
    float acc[16][4];
#pragma unroll
    for (int i = 0; i < 16; i++) {
        acc[i][0] = acc[i][1] = acc[i][2] = acc[i][3] = 0.f;
    }
    for (int ks = 0; ks < 256; ks += 64) {
        __syncthreads();
        for (int i = tid; i < 128 * 16; i += 256) {
            int r = i >> 4, c4 = i & 15;
            int grow = row0 + r;
            float4 v = make_float4(0.f, 0.f, 0.f, 0.f);
            if (grow < M) v = *(const float4*)(A + (size_t)grow * 256 + ks + c4 * 4);
            int kb = c4 * 4;
            As[r * 72 + pidx(kb + 0)] = f2tf(v.x);
            As[r * 72 + pidx(kb + 1)] = f2tf(v.y);
            As[r * 72 + pidx(kb + 2)] = f2tf(v.z);
            As[r * 72 + pidx(kb + 3)] = f2tf(v.w);
        }
        for (int i = tid; i < 64 * 32; i += 256) {
            int k = i >> 5, n4 = i & 31;
            float4 v = *(const float4*)(W + (size_t)(ks + k) * 256 + n0 + n4 * 4);
            int kp = ((k >> 3) << 2) + (k & 3);
            int sl = (k >> 2) & 1;
            unsigned* bp = Bs + kp * 264 + sl;
            bp[(n4 * 4 + 0) * 2] = f2tf(v.x);
            bp[(n4 * 4 + 1) * 2] = f2tf(v.y);
            bp[(n4 * 4 + 2) * 2] = f2tf(v.z);
            bp[(n4 * 4 + 3) * 2] = f2tf(v.w);
        }
        __syncthreads();
#pragma unroll
        for (int k8 = 0; k8 < 8; k8++) {
            uint2 pa = *(uint2*)&As[(wr + g) * 72 + k8 * 8 + t * 2];
            uint2 pb = *(uint2*)&As[(wr + g + 8) * 72 + k8 * 8 + t * 2];
#pragma unroll
            for (int nt = 0; nt < 16; nt++) {
                uint2 bb = *(uint2*)&Bs[(k8 * 4 + t) * 264 + (nt * 8 + g) * 2];
                mma8(acc[nt], pa.x, pb.x, pa.y, pb.y, bb.x, bb.y);
            }
        }
    }
#pragma unroll
    for (int nt = 0; nt < 16; nt++) {
        int c = n0 + nt * 8 + t * 2;
        float2 bv = *(const float2*)(bias + c);
        int r0 = row0 + wr + g, r1 = r0 + 8;
        if (r0 < M) {
            float2 o = make_float2(acc[nt][0] + bv.x, acc[nt][1] + bv.y);
            *(float2*)(C + (size_t)r0 * 256 + c) = o;
        }
        if (r1 < M) {
            float2 o = make_float2(acc[nt][2] + bv.x, acc[nt][3] + bv.y);
            *(float2*)(C + (size_t)r1 * 256 + c) = o;
        }
    }
}

__global__ void init_kernel() {
    int i = blockIdx.x * blockDim.x + threadIdx.x;
    if (i < Nn * 4) {
        g_lmax[i] = 0u;
        g_den[i] = 0.f;
    }
}

// ---------------- fused edge logits via tf32 mma ----------------
__global__ __launch_bounds__(256, 2) void logit_mma_kernel(
    const float* __restrict__ eattr, const float* __restrict__ We_l,
    const float* __restrict__ att_l) {
    extern __shared__ unsigned sm[];
    unsigned* sWe = sm;              // [32 kpair][256 n][2] pitch 520
    unsigned* As  = sm + 32 * 520;   // [128][72]
    float* satt = (float*)(As + 128 * 72);  // 256
    int* sSrc = (int*)(satt + 256);         // 128
    int* sDst = sSrc + 128;                 // 128
    int tid = threadIdx.x, lane = tid & 31, warp = tid >> 5;
    int t = lane & 3, g = lane >> 2, wr = warp * 16;

    for (int i = tid; i < 4096; i += 256) {
        int k = i >> 6, n4 = i & 63;
        float4 v = *(const float4*)(We_l + (size_t)k * 256 + n4 * 4);
        int kp = ((k >> 3) << 2) + (k & 3);
        int sl = (k >> 2) & 1;
        unsigned* bp = sWe + kp * 520 + sl;
        bp[(n4 * 4 + 0) * 2] = f2tf(v.x);
        bp[(n4 * 4 + 1) * 2] = f2tf(v.y);
        bp[(n4 * 4 + 2) * 2] = f2tf(v.z);
        bp[(n4 * 4 + 3) * 2] = f2tf(v.w);
    }
    if (tid < 256) satt[tid] = att_l[tid];

    int ntiles = (EF + 127) / 128;
    for (int tile = blockIdx.x; tile < ntiles; tile += gridDim.x) {
        int base = tile * 128;
        __syncthreads();
        for (int i = tid; i < 128 * 16; i += 256) {
            int r = i >> 4, c4 = i & 15;
            int e = base + r;
            float4 v = make_float4(0.f, 0.f, 0.f, 0.f);
            if (e < Ee)      v = ldcs4(eattr + (size_t)e * 64 + c4 * 4);
            else if (e < EF) v = *(const float4*)(g_loopattr + (size_t)(e - Ee) * 64 + c4 * 4);
            int kb = c4 * 4;
            As[r * 72 + pidx(kb + 0)] = f2tf(v.x);
            As[r * 72 + pidx(kb + 1)] = f2tf(v.y);
            As[r * 72 + pidx(kb + 2)] = f2tf(v.z);
            As[r * 72 + pidx(kb + 3)] = f2tf(v.w);
        }
        if (tid < 128) {
            int e = base + tid;
            int s = 0, d = 0;
            if (e < Ee)      { s = g_src[e]; d = g_dst[e]; }
            else if (e < EF) { s = d = e - Ee; }
            sSrc[tid] = s;
            sDst[tid] = d;
        }
        __syncthreads();

        unsigned a0[8], a1[8], a2[8], a3[8];
#pragma unroll
        for (int k8 = 0; k8 < 8; k8++) {
            uint2 pa = *(uint2*)&As[(wr + g) * 72 + k8 * 8 + t * 2];
            uint2 pb = *(uint2*)&As[(wr + g + 8) * 72 + k8 * 8 + t * 2];
            a0[k8] = pa.x; a2[k8] = pa.y;
            a1[k8] = pb.x; a3[k8] = pb.y;
        }
        int r0 = wr + g, r1 = wr + g + 8;
        int e0 = base + r0, e1 = base + r1;
        int s0 = sSrc[r0], d0 = sDst[r0];
        int s1 = sSrc[r1], d1 = sDst[r1];

#pragma unroll
        for (int h = 0; h < 4; h++) {
            float acc[8][4];
#pragma unroll
            for (int nt = 0; nt < 8; nt++) {
                acc[nt][0] = acc[nt][1] = acc[nt][2] = acc[nt][3] = 0.f;
            }
#pragma unroll
            for (int k8 = 0; k8 < 8; k8++) {
#pragma unroll
                for (int nt = 0; nt < 8; nt++) {
                    uint2 bb = *(uint2*)&sWe[(k8 * 4 + t) * 520 + (h * 64 + nt * 8 + g) * 2];
                    mma8(acc[nt], a0[k8], a1[k8], a2[k8], a3[k8], bb.x, bb.y);
                }
            }
            float p0 = 0.f, p1 = 0.f;
#pragma unroll
            for (int nt = 0; nt < 8; nt++) {
                int c = h * 64 + nt * 8 + t * 2;
                float2 av  = *(float2*)&satt[c];
                float2 xl0 = *(const float2*)(g_XL + (size_t)s0 * 256 + c);
                float2 xr0 = *(const float2*)(g_XR + (size_t)d0 * 256 + c);
                float2 xl1 = *(const float2*)(g_XL + (size_t)s1 * 256 + c);
                float2 xr1 = *(const float2*)(g_XR + (size_t)d1 * 256 + c);
                float v;
                v = acc[nt][0] + xl0.x + xr0.x; v = fmaxf(v, 0.f) + NEG * fminf(v, 0.f); p0 = fmaf(v, av.x, p0);
                v = acc[nt][1] + xl0.y + xr0.y; v = fmaxf(v, 0.f) + NEG * fminf(v, 0.f); p0 = fmaf(v, av.y, p0);
                v = acc[nt][2] + xl1.x + xr1.x; v = fmaxf(v, 0.f) + NEG * fminf(v, 0.f); p1 = fmaf(v, av.x, p1);
                v = acc[nt][3] + xl1.y + xr1.y; v = fmaxf(v, 0.f) + NEG * fminf(v, 0.f); p1 = fmaf(v, av.y, p1);
            }
            p0 += __shfl_xor_sync(0xffffffffu, p0, 1);
            p0 += __shfl_xor_sync(0xffffffffu, p0, 2);
            p1 += __shfl_xor_sync(0xffffffffu, p1, 1);
            p1 += __shfl_xor_sync(0xffffffffu, p1, 2);
            if (t == 0) {
                if (e0 < EF) {
                    g_logits[e0 * 4 + h] = p0;
                    atomicMax(&g_lmax[d0 * 4 + h], ordkey(p0));
                }
                if (e1 < EF) {
                    g_logits[e1 * 4 + h] = p1;
                    atomicMax(&g_lmax[d1 * 4 + h], ordkey(p1));
                }
            }
        }
    }
}

// ---------------- edge-parallel alpha: one edge per thread, float4 over heads ----
__global__ void alpha_kernel() {
    int e = blockIdx.x * blockDim.x + threadIdx.x;
    if (e >= EF) return;
    int d = (e < Ee) ? g_dst[e] : (e - Ee);
    float4 lg = *(float4*)(g_logits + (size_t)e * 4);
    float4 a;
    a.x = __expf(lg.x - orddec(g_lmax[d * 4 + 0]));
    a.y = __expf(lg.y - orddec(g_lmax[d * 4 + 1]));
    a.z = __expf(lg.z - orddec(g_lmax[d * 4 + 2]));
    a.w = __expf(lg.w - orddec(g_lmax[d * 4 + 3]));
    *(float4*)(g_logits + (size_t)e * 4) = a;
    atomicAdd(&g_den[d * 4 + 0], a.x);
    atomicAdd(&g_den[d * 4 + 1], a.y);
    atomicAdd(&g_den[d * 4 + 2], a.z);
    atomicAdd(&g_den[d * 4 + 3], a.w);
}

// ---------------- per-node aggregation: 4 nodes/block, 64-thread groups, float4 ----
__global__ __launch_bounds__(256, 4) void agg_kernel(
    const float* __restrict__ bias, float* __restrict__ out) {
    __shared__ int   sSrc[4][32];
    __shared__ float4 sAl[4][32];
    __shared__ float sInv[4][4];
    int tid = threadIdx.x;
    int lt = tid & 63, g = tid >> 6;
    int n = blockIdx.x * 4 + g;
    int s = g_rowstart[n], e1 = g_rowstart[n + 1];
    int deg = e1 - s;
    if (lt < 4) sInv[g][lt] = 1.0f / g_den[n * 4 + lt];
    BARG(g + 1);
    int c4 = lt * 4;
    int h = lt >> 4;
    float4 acc = make_float4(0.f, 0.f, 0.f, 0.f);
    for (int b0 = 0; b0 < deg; b0 += 32) {
        int cnt = min(32, deg - b0);
        if (lt < cnt) {
            int e = g_csr[s + b0 + lt];
            sSrc[g][lt] = (e < Ee) ? g_src[e] : (e - Ee);
            float4 a4 = *(const float4*)(g_logits + (size_t)e * 4);
            a4.x *= sInv[g][0];
            a4.y *= sInv[g][1];
            a4.z *= sInv[g][2];
            a4.w *= sInv[g][3];
            sAl[g][lt] = a4;
        }
        BARG(g + 1);
#pragma unroll 4
        for (int j = 0; j < cnt; j++) {
            float a = ((const float*)&sAl[g][j])[h];
            float4 xv = *(const float4*)(g_XL + (size_t)sSrc[g][j] * 256 + c4);
            acc.x = fmaf(a, xv.x, acc.x);
            acc.y = fmaf(a, xv.y, acc.y);
            acc.z = fmaf(a, xv.z, acc.z);
            acc.w = fmaf(a, xv.w, acc.w);
        }
        BARG(g + 1);
    }
    float4 bv = *(const float4*)(bias + c4);
    acc.x += bv.x; acc.y += bv.y; acc.z += bv.z; acc.w += bv.w;
    *(float4*)(out + (size_t)n * 256 + c4) = acc;
}

// ---------------- launch ----------------
extern "C" void kernel_launch(void* const* d_in, const int* in_sizes, int n_in,
                              void* d_out, int out_size) {
    const float* x     = (const float*)d_in[0];
    const void*  ei    = d_in[1];
    const float* eattr = (const float*)d_in[2];
    const float* Wl    = (const float*)d_in[3];
    const float* bl    = (const float*)d_in[4];
    const float* Wr    = (const float*)d_in[5];
    const float* br    = (const float*)d_in[6];
    const float* We    = (const float*)d_in[7];
    const float* att   = (const float*)d_in[8];
    const float* bias  = (const float*)d_in[9];
    float* out = (float*)d_out;

    const int LOGIT_SMEM = (32 * 520 + 128 * 72) * 4 + 256 * 4 + 128 * 4 * 2;
    const int XFORM_SMEM = (128 * 72 + 32 * 264) * 4;
    cudaFuncSetAttribute(logit_mma_kernel, cudaFuncAttributeMaxDynamicSharedMemorySize, LOGIT_SMEM);
    cudaFuncSetAttribute(xform_kernel, cudaFuncAttributeMaxDynamicSharedMemorySize, XFORM_SMEM);

    void *pXL, *pXR, *px1, *px2;
    cudaGetSymbolAddress(&pXL, g_XL);
    cudaGetSymbolAddress(&pXR, g_XR);
    cudaGetSymbolAddress(&px1, g_x1);
    cudaGetSymbolAddress(&px2, g_x2);

    const int EB = (Ee + 255) / 256;
    const int NB = (Nn + 255) / 256;

    detect_kernel<<<1, 1>>>(ei);
    convert_kernel<<<EB, 256>>>(ei);
    zero_counts_kernel<<<NB, 256>>>();
    count_kernel<<<EB, 256>>>();
    scan_kernel<<<1, 1024>>>();
    copy_cursor_kernel<<<NB, 256>>>();
    fill_kernel<<<EB, 256>>>();
    selfplace_kernel<<<NB, 256>>>();
    loopattr_kernel<<<Nn, 64>>>(eattr);

    const float* xin = x;
    for (int l = 0; l < 3; l++) {
        float* xout = (l == 0) ? (float*)px1 : (l == 1) ? (float*)px2 : out;
        dim3 gg(2, (Nn + 127) / 128, 2);
        xform_kernel<<<gg, 256, XFORM_SMEM>>>(
            xin, Wl + (size_t)l * 65536, bl + l * 256,
            Wr + (size_t)l * 65536, br + l * 256,
            (float*)pXL, (float*)pXR, Nn);
        init_kernel<<<(Nn * 4 + 255) / 256, 256>>>();
        logit_mma_kernel<<<296, 256, LOGIT_SMEM>>>(eattr, We + (size_t)l * 16384, att + l * 256);
        alpha_kernel<<<(EF + 255) / 256, 256>>>();
        agg_kernel<<<(Nn + 3) / 4, 256>>>(bias + l * 256, xout);
        xin = xout;
    }
}